// round 1
// baseline (speedup 1.0000x reference)
#include <cuda_runtime.h>
#include <math.h>

#define NMAX 8192
#define TJ 1024          // j-tile per block
#define BT 256           // threads per block
#define DPSI_T 0.05f
#define MSE_W 10.0f
#define LEPS 1e-7f

// Scratch (no allocations allowed)
__device__ float g_d[NMAX];                 // d[i] = pred[i] - logit(psi[i])
__device__ double g_sum;                    // sum of valid squared residuals
__device__ unsigned long long g_cnt;        // n_valid
__device__ double g_bce;                    // sum of BCE terms

__global__ void k_zero() {
    g_sum = 0.0;
    g_cnt = 0ull;
    g_bce = 0.0;
}

__device__ __forceinline__ float warp_sum_f(float v) {
    #pragma unroll
    for (int o = 16; o > 0; o >>= 1) v += __shfl_down_sync(0xFFFFFFFFu, v, o);
    return v;
}

// Prep: compute d[i] and the BCE partial sums.
__global__ void k_prep(const float* __restrict__ pred,
                       const float* __restrict__ psi, int n) {
    int i = blockIdx.x * blockDim.x + threadIdx.x;
    float bce = 0.0f;
    if (i < n) {
        float p  = psi[i];
        float pc = fminf(fmaxf(p, LEPS), 1.0f - LEPS);
        float lg = logf(pc) - log1pf(-pc);
        float x  = pred[i];
        g_d[i] = x - lg;
        // stable BCE-with-logits term
        bce = fmaxf(x, 0.0f) - x * p + log1pf(expf(-fabsf(x)));
    }
    // block reduce bce
    __shared__ float sm[BT / 32];
    float w = warp_sum_f(bce);
    int lane = threadIdx.x & 31, wid = threadIdx.x >> 5;
    if (lane == 0) sm[wid] = w;
    __syncthreads();
    if (wid == 0) {
        float v = (lane < (blockDim.x >> 5)) ? sm[lane] : 0.0f;
        v = warp_sum_f(v);
        if (lane == 0) atomicAdd(&g_bce, (double)v);
    }
}

// Pairwise: grid (n/BT, n/TJ). Each thread owns one i, loops over a j-tile
// held in shared memory (broadcast reads across the warp).
__global__ void k_pair(const float* __restrict__ psi, int n) {
    __shared__ float2 sh[TJ];          // (psi_j, d_j)
    int i  = blockIdx.x * BT + threadIdx.x;
    int j0 = blockIdx.y * TJ;

    for (int t = threadIdx.x; t < TJ; t += BT) {
        int j = j0 + t;
        float pj = (j < n) ? psi[j]  : 1e30f;   // sentinel: invalid & dd irrelevant
        float dj = (j < n) ? g_d[j]  : 0.0f;
        sh[t] = make_float2(pj, dj);
    }
    __syncthreads();

    float psi_i = (i < n) ? psi[i] : -1e30f;
    float d_i   = (i < n) ? g_d[i] : 0.0f;

    float acc = 0.0f;
    int   cnt = 0;
    if (i < n) {
        #pragma unroll 8
        for (int t = 0; t < TJ; t++) {
            float2 v  = sh[t];
            float dpsi = psi_i - v.x;
            float dd   = d_i   - v.y;
            if (fabsf(dpsi) >= DPSI_T) { acc += dd * dd; cnt += 1; }
        }
    }

    // block reduce acc + cnt
    __shared__ float  sa[BT / 32];
    __shared__ int    sc[BT / 32];
    float wa = warp_sum_f(acc);
    int   wc = cnt;
    #pragma unroll
    for (int o = 16; o > 0; o >>= 1) wc += __shfl_down_sync(0xFFFFFFFFu, wc, o);
    int lane = threadIdx.x & 31, wid = threadIdx.x >> 5;
    if (lane == 0) { sa[wid] = wa; sc[wid] = wc; }
    __syncthreads();
    if (wid == 0) {
        float va = (lane < (BT >> 5)) ? sa[lane] : 0.0f;
        int   vc = (lane < (BT >> 5)) ? sc[lane] : 0;
        va = warp_sum_f(va);
        #pragma unroll
        for (int o = 16; o > 0; o >>= 1) vc += __shfl_down_sync(0xFFFFFFFFu, vc, o);
        if (lane == 0) {
            atomicAdd(&g_sum, (double)va);
            atomicAdd(&g_cnt, (unsigned long long)vc);
        }
    }
}

__global__ void k_fin(const int* __restrict__ flag, float* __restrict__ out, int n) {
    double loss = g_bce / (double)n;
    if (*flag == 0) {
        unsigned long long c = g_cnt;
        if (c > 0ull) loss += (double)MSE_W * (g_sum / (double)c);
    }
    out[0] = (float)loss;
}

extern "C" void kernel_launch(void* const* d_in, const int* in_sizes, int n_in,
                              void* d_out, int out_size) {
    const float* pred = (const float*)d_in[0];
    const float* psi  = (const float*)d_in[1];
    const int*   flag = (const int*)d_in[2];
    float* out = (float*)d_out;
    int n = in_sizes[0];

    k_zero<<<1, 1>>>();
    k_prep<<<(n + BT - 1) / BT, BT>>>(pred, psi, n);
    dim3 grid((n + BT - 1) / BT, (n + TJ - 1) / TJ);
    k_pair<<<grid, BT>>>(psi, n);
    k_fin<<<1, 1>>>(flag, out, n);
}

// round 15
// speedup vs baseline: 1.5631x; 1.5631x over previous
#include <cuda_runtime.h>
#include <math.h>

#define NMAX    8192
#define BT      256        // threads per block (i-range per block)
#define G       512        // group granularity (j-tile width, i-group height)
#define SUB     (G / BT)   // i-subblocks per group = 2
#define MAXBLK  512
#define DPSI_T  0.05f
#define MSE_W   10.0f
#define LEPS    1e-7f

// Scratch — per-block partials are fully rewritten every run (no zeroing needed).
__device__ float              g_pa[MAXBLK];   // weighted sq-residual partial
__device__ int                g_pc[MAXBLK];   // weighted valid-count partial
__device__ float              g_pb[MAXBLK];   // BCE partial (diag blocks only, else 0)
__device__ unsigned int       g_ctr = 0;      // finalize ticket (self-resetting)

__device__ __forceinline__ float logit_f(float p) {
    float pc = fminf(fmaxf(p, LEPS), 1.0f - LEPS);
    return logf(pc) - log1pf(-pc);
}

__device__ __forceinline__ float warp_sum_f(float v) {
    #pragma unroll
    for (int o = 16; o > 0; o >>= 1) v += __shfl_down_sync(0xFFFFFFFFu, v, o);
    return v;
}
__device__ __forceinline__ int warp_sum_i(int v) {
    #pragma unroll
    for (int o = 16; o > 0; o >>= 1) v += __shfl_down_sync(0xFFFFFFFFu, v, o);
    return v;
}
__device__ __forceinline__ double warp_sum_d(double v) {
    #pragma unroll
    for (int o = 16; o > 0; o >>= 1) v += __shfl_down_sync(0xFFFFFFFFu, v, o);
    return v;
}

__global__ void __launch_bounds__(BT)
k_all(const float* __restrict__ pred, const float* __restrict__ psi,
      const int* __restrict__ flag, float* __restrict__ out,
      int n, int gc, int nblocks) {
    // Decode (R, C, sub) from blockIdx: upper-triangular group tiles.
    int tile = blockIdx.x >> 1;
    int sub  = blockIdx.x & 1;
    int R = 0, rem = tile, rowlen = gc;
    while (rem >= rowlen) { rem -= rowlen; R++; rowlen--; }
    int C = R + rem;

    int i  = R * G + sub * BT + threadIdx.x;
    int j0 = C * G;

    __shared__ float2 sh[G];   // (psi_j, d_j), read as float4 (2 pairs)

    const float QNAN = __int_as_float(0x7fffffff);

    // Fill the j-tile: each thread computes d_j for 2 j's.
    #pragma unroll
    for (int t = threadIdx.x; t < G; t += BT) {
        int j = j0 + t;
        float pj = QNAN, dj = 0.0f;        // NaN => all comparisons false => excluded
        if (j < n) {
            pj = psi[j];
            dj = pred[j] - logit_f(pj);
        }
        sh[t] = make_float2(pj, dj);
    }

    // Own i values (+ BCE term, counted once via the diagonal tile).
    float psi_i = QNAN, d_i = 0.0f, bce = 0.0f;
    if (i < n) {
        psi_i = psi[i];
        float x = pred[i];
        d_i = x - logit_f(psi_i);
        if (R == C)
            bce = fmaxf(x, 0.0f) - x * psi_i + log1pf(expf(-fabsf(x)));
    }
    __syncthreads();

    // Pairwise inner loop over the j-tile, 2 pairs per LDS.128.
    const float4* sv = reinterpret_cast<const float4*>(sh);
    float acc = 0.0f;
    int   cnt = 0;
    #pragma unroll 8
    for (int t = 0; t < G / 2; t++) {
        float4 v = sv[t];
        float dp0 = psi_i - v.x, dd0 = d_i - v.y;
        if (fabsf(dp0) >= DPSI_T) { acc += dd0 * dd0; cnt++; }
        float dp1 = psi_i - v.z, dd1 = d_i - v.w;
        if (fabsf(dp1) >= DPSI_T) { acc += dd1 * dd1; cnt++; }
    }

    int w = (C > R) ? 2 : 1;    // off-diagonal tiles mirror-counted

    // Block reduction of (acc, cnt, bce).
    const int NW = BT >> 5;
    __shared__ float sa[NW];
    __shared__ int   sc[NW];
    __shared__ float sb[NW];
    float wa = warp_sum_f(acc);
    int   wc = warp_sum_i(cnt);
    float wb = warp_sum_f(bce);
    int lane = threadIdx.x & 31, wid = threadIdx.x >> 5;
    if (lane == 0) { sa[wid] = wa; sc[wid] = wc; sb[wid] = wb; }
    __syncthreads();
    __shared__ int s_last;
    if (wid == 0) {
        float va = (lane < NW) ? sa[lane] : 0.0f;
        int   vc = (lane < NW) ? sc[lane] : 0;
        float vb = (lane < NW) ? sb[lane] : 0.0f;
        va = warp_sum_f(va);
        vc = warp_sum_i(vc);
        vb = warp_sum_f(vb);
        if (lane == 0) {
            g_pa[blockIdx.x] = va * (float)w;
            g_pc[blockIdx.x] = vc * w;
            g_pb[blockIdx.x] = vb;
            __threadfence();
            unsigned int t = atomicAdd(&g_ctr, 1u);
            s_last = (t == (unsigned int)(nblocks - 1)) ? 1 : 0;
        }
    }
    __syncthreads();

    // Last block finalizes.
    if (s_last) {
        double da = 0.0, db = 0.0;
        long long dc = 0;
        for (int k = threadIdx.x; k < nblocks; k += BT) {
            da += (double)g_pa[k];
            dc += (long long)g_pc[k];
            db += (double)g_pb[k];
        }
        __shared__ double ra[NW], rb[NW];
        __shared__ long long rc[NW];
        da = warp_sum_d(da);
        db = warp_sum_d(db);
        #pragma unroll
        for (int o = 16; o > 0; o >>= 1) dc += __shfl_down_sync(0xFFFFFFFFu, dc, o);
        if (lane == 0) { ra[wid] = da; rb[wid] = db; rc[wid] = dc; }
        __syncthreads();
        if (wid == 0) {
            double va = (lane < NW) ? ra[lane] : 0.0;
            double vb = (lane < NW) ? rb[lane] : 0.0;
            long long vc = (lane < NW) ? rc[lane] : 0;
            va = warp_sum_d(va);
            vb = warp_sum_d(vb);
            #pragma unroll
            for (int o = 16; o > 0; o >>= 1) vc += __shfl_down_sync(0xFFFFFFFFu, vc, o);
            if (lane == 0) {
                double loss = vb / (double)n;
                if (*flag == 0 && vc > 0)
                    loss += (double)MSE_W * (va / (double)vc);
                out[0] = (float)loss;
                g_ctr = 0;   // reset for next replay
            }
        }
    }
}

extern "C" void kernel_launch(void* const* d_in, const int* in_sizes, int n_in,
                              void* d_out, int out_size) {
    const float* pred = (const float*)d_in[0];
    const float* psi  = (const float*)d_in[1];
    const int*   flag = (const int*)d_in[2];
    float* out = (float*)d_out;
    int n = in_sizes[0];

    int gc      = (n + G - 1) / G;            // number of 512-groups
    int tiles   = gc * (gc + 1) / 2;          // upper-triangular group tiles
    int nblocks = tiles * SUB;

    k_all<<<nblocks, BT>>>(pred, psi, flag, out, n, gc, nblocks);
}